// round 9
// baseline (speedup 1.0000x reference)
#include <cuda_runtime.h>
#include <cuda_bf16.h>
#include <cstdint>

// VQ-VAE bottleneck — 2-pass split-bf16 HMMA distance GEMM + exact rescore.
// Round 9 = round 8 with the A-fragment addressing bug fixed: the ldmatrix
// base address dropped m_base (warp's 16-row slice), so every warp scored
// rows 0-15. One-line fix; all else identical to isolate the repair.
//
// Per CTA: 128 positions x 512 codewords, 2 CTAs/SM (smem ~100KB).
//   s_k = (a1 + a2) . e1 + ||e_k||^2,  a = -2z  (a1,a2 = bf16 hi/lo; e1 = bf16(e))
//   dropped |a.e2_k| <= ||a_m|| * max_k ||e2_k||  (exact per-row bound)
//   gap >= MARGIN_m -> approx argmin == reference argmin (proved).
//   gap <  MARGIN_m -> rescore ALL 512 k bit-exactly:
//       d = RN(RN(Z+B_k) - 2*seqFMA(z,e_k)), (d,k)-lex min   (validated r2-r7)
// Output: straight-through RN(x + RN(q-x)); loss = RN(L + RN(0.25L)), L = SSE/N.

#define CDIM    64
#define KCODES  512
#define HW      4096
#define NELEM   8388608
#define THREADS 256
#define P_CTA   128
#define GRIDSZ  1024

typedef unsigned long long u64;
typedef unsigned int u32;

__device__ float g_loss_sum;
__device__ u32   g_done;

// smem layout (bytes); B/A tiles use SW128 swizzle on 128B rows
#define OFF_B1   0          // 512 x 128B = 65536
#define OFF_A(h) (65536 + (h) * 16384)   // 2 x 128 x 128B
#define OFF_E2   98304      // 512 f32  ||e_k||^2 (ref rounding)
#define OFF_ZS   100352     // 128 f32  Z per row (ref rounding)
#define OFF_KB   100864     // 128 u32  kbest
#define OFF_FL   101376     // 128 u32  flags
#define OFF_EM   101888     // 1 u32    max ||e2_k||^2 bits
#define SMEM_SZ  102400

#define SW(o) ((o) ^ (((o) >> 3) & 0x70))

__device__ __forceinline__ u32 smem_u32(const void* p) {
    u32 a; asm("{ .reg .u64 t; cvta.to.shared.u64 t, %1; cvt.u32.u64 %0, t; }" : "=r"(a) : "l"(p));
    return a;
}
__device__ __forceinline__ void ldsm4(u32 addr, u32& r0, u32& r1, u32& r2, u32& r3) {
    asm volatile("ldmatrix.sync.aligned.m8n8.x4.shared.b16 {%0,%1,%2,%3}, [%4];"
                 : "=r"(r0), "=r"(r1), "=r"(r2), "=r"(r3) : "r"(addr));
}
__device__ __forceinline__ void mma_bf16(float* d, const u32* a, u32 b0, u32 b1) {
    asm volatile("mma.sync.aligned.m16n8k16.row.col.f32.bf16.bf16.f32 "
                 "{%0,%1,%2,%3}, {%4,%5,%6,%7}, {%8,%9}, {%0,%1,%2,%3};"
                 : "+f"(d[0]), "+f"(d[1]), "+f"(d[2]), "+f"(d[3])
                 : "r"(a[0]), "r"(a[1]), "r"(a[2]), "r"(a[3]), "r"(b0), "r"(b1));
}
__device__ __forceinline__ u32 ord(u32 fb) {
    return fb ^ ((fb & 0x80000000u) ? 0xFFFFFFFFu : 0x80000000u);
}
__device__ __forceinline__ float dec(u32 o) {
    return __uint_as_float((o & 0x80000000u) ? (o ^ 0x80000000u) : ~o);
}
__device__ __forceinline__ void upd(u64& m1, u64& m2, u64 key) {
    if (key < m1) { m2 = m1; m1 = key; } else if (key < m2) { m2 = key; }
}
__device__ __forceinline__ void merge2(u64& m1, u64& m2, u64 q1, u64 q2) {
    u64 lo = m1 < q1 ? m1 : q1;
    u64 hi = m1 < q1 ? q1 : m1;
    u64 s2 = m2 < q2 ? m2 : q2;
    m1 = lo; m2 = hi < s2 ? hi : s2;
}

extern __shared__ char smc[];

__global__ __launch_bounds__(THREADS, 2)
void vq_main_kernel(const float* __restrict__ x,
                    const float* __restrict__ cb,
                    float* __restrict__ out,
                    int loss_idx) {
    const u32 sb   = smem_u32(smc);
    const int tid  = threadIdx.x;
    const int w    = tid >> 5;
    const int lane = tid & 31;

    float* e2s = (float*)(smc + OFF_E2);
    float* Zs  = (float*)(smc + OFF_ZS);
    u32*   kbs = (u32*)(smc + OFF_KB);
    u32*   fls = (u32*)(smc + OFF_FL);
    u32*   emw = (u32*)(smc + OFF_EM);

    const int b   = blockIdx.x >> 5;
    const int hw0 = (blockIdx.x & 31) * P_CTA;
    const float* xrow = x + (size_t)b * CDIM * HW + hw0;

    if (tid == 0) *emw = 0u;

    // ---- A tiles: a = -2z split to bf16 hi/lo, row p, 128B rows, SW128 ----
    for (int idx = tid; idx < CDIM * P_CTA; idx += THREADS) {
        int c = idx >> 7, p = idx & 127;
        float v = xrow[(size_t)c * HW + p];
        float a = -2.0f * v;                                  // exact
        __nv_bfloat16 a1 = __float2bfloat16_rn(a);
        __nv_bfloat16 a2 = __float2bfloat16_rn(__fadd_rn(a, -__bfloat162float(a1)));
        u32 o = SW((u32)(p * 128 + c * 2));
        *(__nv_bfloat16*)(smc + OFF_A(0) + o) = a1;
        *(__nv_bfloat16*)(smc + OFF_A(1) + o) = a2;
    }
    // ---- B tile: e1 = bf16(e), row k, SW128 ----
    for (int idx = tid; idx < KCODES * CDIM; idx += THREADS) {
        int k = idx >> 6, c = idx & 63;
        u32 o = SW((u32)(k * 128 + c * 2));
        *(__nv_bfloat16*)(smc + OFF_B1 + o) = __float2bfloat16_rn(cb[idx]);
    }
    __syncthreads();

    // ---- e2s (ref order), E2MAX = max_k ||e - bf16(e)||^2 ; Z per row ----
    for (int k = tid; k < KCODES; k += THREADS) {
        const float* ek = cb + k * CDIM;
        float s = 0.0f, rn = 0.0f;
        #pragma unroll
        for (int c = 0; c < CDIM; c++) {
            float e = ek[c];
            s = __fadd_rn(s, __fmul_rn(e, e));
            float r = e - __bfloat162float(__float2bfloat16_rn(e));
            rn += r * r;
        }
        e2s[k] = s;
        atomicMax(emw, __float_as_uint(rn));     // rn >= 0: bits monotone
    }
    if (tid < P_CTA) {
        float s = 0.0f;
        #pragma unroll
        for (int c = 0; c < CDIM; c++) {
            float zv = xrow[(size_t)c * HW + tid];
            s = __fadd_rn(s, __fmul_rn(zv, zv));
        }
        Zs[tid] = s;
    }
    __syncthreads();

    // ---- HMMA mainloop: warp w owns rows [16w,16w+16), 16 chunks of 32 cols ----
    const int m_base = w * 16;
    const int g      = lane >> 2;
    const int t4     = lane & 3;

    // A fragments: 2 halves x 4 k-steps.
    // FIX (r8 bug): base row is m_base + a_r, not a_r. XOR mask unchanged:
    // m_base % 16 == 0 so ((m_base + a_r) & 7) == (a_r & 7).
    u32 afr[2][4][4];
    {
        int a_r = lane & 15, a_c8 = (lane >> 4) << 3;
        u32 xm  = (u32)((a_r & 7) << 4);
        #pragma unroll
        for (int h = 0; h < 2; h++) {
            u32 lin = sb + OFF_A(h) + (u32)((m_base + a_r) * 128 + a_c8 * 2);
            #pragma unroll
            for (int ks = 0; ks < 4; ks++)
                ldsm4((lin + ks * 32) ^ xm,
                      afr[h][ks][0], afr[h][ks][1], afr[h][ks][2], afr[h][ks][3]);
        }
    }

    const int b_r = (lane & 7) + ((lane >> 4) << 3);
    const int b_c = ((lane >> 3) & 1) << 3;
    const u32 bxm  = (u32)((b_r & 7) << 4);
    const u32 blin = sb + OFF_B1 + (u32)(b_r * 128 + b_c * 2);

    u64 mA1 = ~0ull, mA2 = ~0ull;       // row m_base+g
    u64 mB1 = ~0ull, mB2 = ~0ull;       // row m_base+g+8

    #pragma unroll 1
    for (int nc = 0; nc < 16; nc++) {   // 32 codewords per chunk
        float acc[4][4];
        #pragma unroll
        for (int i = 0; i < 4; i++)
            #pragma unroll
            for (int j = 0; j < 4; j++) acc[i][j] = 0.0f;

        u32 cbase = blin + (u32)(nc * 4096);
        #pragma unroll
        for (int ks = 0; ks < 4; ks++) {
            #pragma unroll
            for (int pr = 0; pr < 2; pr++) {
                u32 b0, b1, b2, b3;
                ldsm4((cbase + pr * 2048 + ks * 32) ^ bxm, b0, b1, b2, b3);
                mma_bf16(acc[2 * pr],     afr[0][ks], b0, b1);   // a1.e1
                mma_bf16(acc[2 * pr],     afr[1][ks], b0, b1);   // a2.e1
                mma_bf16(acc[2 * pr + 1], afr[0][ks], b2, b3);
                mma_bf16(acc[2 * pr + 1], afr[1][ks], b2, b3);
            }
        }
        #pragma unroll
        for (int nt = 0; nt < 4; nt++) {
            int col0 = nc * 32 + nt * 8 + 2 * t4;
            float e20 = e2s[col0], e21 = e2s[col0 + 1];
            float s0 = acc[nt][0] + e20;
            float s1 = acc[nt][1] + e21;
            float s2 = acc[nt][2] + e20;
            float s3 = acc[nt][3] + e21;
            upd(mA1, mA2, ((u64)ord(__float_as_uint(s0)) << 32) | (u32)col0);
            upd(mA1, mA2, ((u64)ord(__float_as_uint(s1)) << 32) | (u32)(col0 + 1));
            upd(mB1, mB2, ((u64)ord(__float_as_uint(s2)) << 32) | (u32)col0);
            upd(mB1, mB2, ((u64)ord(__float_as_uint(s3)) << 32) | (u32)(col0 + 1));
        }
    }

    #pragma unroll
    for (int o = 1; o <= 2; o <<= 1) {
        merge2(mA1, mA2, __shfl_xor_sync(0xffffffffu, mA1, o),
                         __shfl_xor_sync(0xffffffffu, mA2, o));
        merge2(mB1, mB2, __shfl_xor_sync(0xffffffffu, mB1, o),
                         __shfl_xor_sync(0xffffffffu, mB2, o));
    }
    if (t4 == 0) {
        float e2m = __fsqrt_rn(__uint_as_float(*emw)) * 1.02f;
        int r0 = m_base + g, r1 = m_base + g + 8;
        float mg0 = 2.0f * (2.02f * __fsqrt_rn(Zs[r0]) * e2m + 1.1e-5f);
        float mg1 = 2.0f * (2.02f * __fsqrt_rn(Zs[r1]) * e2m + 1.1e-5f);
        kbs[r0] = (u32)(mA1 & 0x1FFu);
        kbs[r1] = (u32)(mB1 & 0x1FFu);
        fls[r0] = (dec((u32)(mA2 >> 32)) - dec((u32)(mA1 >> 32))) < mg0;
        fls[r1] = (dec((u32)(mB2 >> 32)) - dec((u32)(mB1 >> 32))) < mg1;
    }
    __syncwarp();

    // ---- exact rescore of flagged rows: whole warp, all 512 k, 4-way ILP ----
    for (int r = 0; r < 16; r++) {
        int row = m_base + r;
        if (!fls[row]) continue;
        const float* xz = xrow + row;
        float Zp = Zs[row];
        u64 best = ~0ull;
        #pragma unroll 1
        for (int jj = 0; jj < 4; jj++) {
            int k0 = lane + 128 * jj;                 // k0, +32, +64, +96
            const float* e0 = cb + (size_t)k0 * CDIM;
            float m0 = 0.f, m1 = 0.f, m2 = 0.f, m3 = 0.f;
            #pragma unroll
            for (int c = 0; c < CDIM; c++) {          // c ascending per chain
                float zc = __ldg(xz + (size_t)c * HW);
                m0 = __fmaf_rn(zc, __ldg(e0 + c),          m0);
                m1 = __fmaf_rn(zc, __ldg(e0 + 2048 + c),   m1);
                m2 = __fmaf_rn(zc, __ldg(e0 + 4096 + c),   m2);
                m3 = __fmaf_rn(zc, __ldg(e0 + 6144 + c),   m3);
            }
            float mm[4] = { m0, m1, m2, m3 };
            #pragma unroll
            for (int i = 0; i < 4; i++) {
                int k = k0 + 32 * i;
                float tt = __fadd_rn(Zp, e2s[k]);
                float d  = __fadd_rn(tt, -2.0f * mm[i]);
                u64 key = ((u64)__float_as_uint(d) << 32) | (u32)k;   // d > 0
                if (key < best) best = key;
            }
        }
        #pragma unroll
        for (int o = 16; o; o >>= 1) {
            u64 v = __shfl_xor_sync(0xffffffffu, best, o);
            if (v < best) best = v;
        }
        if (lane == 0) kbs[row] = (u32)(best & 0x1FFu);
    }
    __syncthreads();

    // ---- writeback: straight-through RN(x + RN(q-x)) + SSE ----
    {
        int p = tid & 127, ch = tid >> 7;
        u32 kb = kbs[p];
        const float* qk = cb + (size_t)kb * CDIM;
        float* op = out + (size_t)b * CDIM * HW + hw0 + p;
        const float* ip = xrow + p;
        float sse = 0.0f;
        #pragma unroll 8
        for (int c = ch * 32; c < ch * 32 + 32; c++) {
            float zv   = __ldg(ip + (size_t)c * HW);
            float qv   = __ldg(qk + c);
            float diff = __fadd_rn(qv, -zv);
            op[(size_t)c * HW] = __fadd_rn(zv, diff);
            sse = __fadd_rn(sse, __fmul_rn(diff, diff));
        }
        #pragma unroll
        for (int o = 16; o; o >>= 1) sse += __shfl_xor_sync(0xffffffffu, sse, o);
        if (lane == 0) atomicAdd(&g_loss_sum, sse);
    }

    // ---- fused finalize, reset for next graph replay ----
    __syncthreads();
    if (tid == 0) {
        __threadfence();
        u32 done = atomicAdd(&g_done, 1u);
        if (done == gridDim.x - 1) {
            float L = atomicAdd(&g_loss_sum, 0.0f) * (1.0f / (float)NELEM);
            if (loss_idx >= 0)
                out[loss_idx] = __fadd_rn(L, 0.25f * L);
            g_loss_sum = 0.0f;
            g_done     = 0u;
            __threadfence();
        }
    }
}

extern "C" void kernel_launch(void* const* d_in, const int* in_sizes, int n_in,
                              void* d_out, int out_size) {
    const float* x   = (const float*)d_in[0];
    const float* cb  = (const float*)d_in[1];
    float*       out = (float*)d_out;

    cudaFuncSetAttribute(vq_main_kernel,
                         cudaFuncAttributeMaxDynamicSharedMemorySize, SMEM_SZ);
    int loss_idx = (out_size > NELEM) ? (out_size - 1) : -1;
    vq_main_kernel<<<GRIDSZ, THREADS, SMEM_SZ>>>(x, cb, out, loss_idx);
}

// round 10
// speedup vs baseline: 6.8026x; 6.8026x over previous
#include <cuda_runtime.h>
#include <cuda_bf16.h>
#include <cstdint>

// VQ-VAE bottleneck — 3-pass split-bf16 HMMA distance GEMM (k in 2 halves,
// 2 CTAs/SM) + COALESCED exact rescore via transposed codebook scratch.
//
// Round 10 fixes round 9's two rescore pathologies:
//   (1) 2-pass margin was ~6e-4 -> flag flood. Back to 3-pass (a1e1+a2e1+a1e2):
//       dropped |a2.e2| ~ 1e-7, fixed MARGIN=6e-5 (validated round 7).
//   (2) rescore read codeword rows lane-strided (32 wavefronts/LDG). Now reads
//       cbT[c][k] (transposed fp32 copy in __device__ scratch): coalesced.
//
//   s_k = D + ||e_k||^2; gap >= MARGIN -> approx argmin == reference argmin.
//   flagged rows rescore ALL 512 k bit-exactly:
//       d = RN(RN(Z+B_k) - 2*seqFMA(z,e_k)), (d,k)-lex min (validated r2-r9).
// Output: straight-through RN(x + RN(q-x)); loss = RN(L + RN(0.25L)), L = SSE/N.

#define CDIM    64
#define KCODES  512
#define HW      4096
#define NELEM   8388608
#define THREADS 256
#define P_CTA   128
#define GRIDSZ  1024
#define MARGIN  6e-5f
#define KHALF   256

typedef unsigned long long u64;
typedef unsigned int u32;

__device__ float g_loss_sum;
__device__ u32   g_done;
__device__ float g_cbT[CDIM * KCODES];   // transposed codebook [c][k], scratch

// smem layout (bytes); tiles use SW128 swizzle on 128B rows
#define OFF_B1   0          // 256 x 128B = 32768 (bf16 hi of e, current half)
#define OFF_B2   32768      // 256 x 128B          (bf16 lo of e, current half)
#define OFF_A(h) (65536 + (h) * 16384)   // 2 x 128 x 128B (bf16 hi/lo of -2z)
#define OFF_E2   98304      // 512 f32  ||e_k||^2 (ref rounding)
#define OFF_ZS   100352     // 128 f32  Z per row (ref rounding)
#define OFF_KB   100864     // 128 u32  kbest
#define OFF_FL   101376     // 128 u32  flags
#define SMEM_SZ  101888

#define SW(o) ((o) ^ (((o) >> 3) & 0x70))

__device__ __forceinline__ u32 smem_u32(const void* p) {
    u32 a; asm("{ .reg .u64 t; cvta.to.shared.u64 t, %1; cvt.u32.u64 %0, t; }" : "=r"(a) : "l"(p));
    return a;
}
__device__ __forceinline__ void ldsm4(u32 addr, u32& r0, u32& r1, u32& r2, u32& r3) {
    asm volatile("ldmatrix.sync.aligned.m8n8.x4.shared.b16 {%0,%1,%2,%3}, [%4];"
                 : "=r"(r0), "=r"(r1), "=r"(r2), "=r"(r3) : "r"(addr));
}
__device__ __forceinline__ void mma_bf16(float* d, const u32* a, u32 b0, u32 b1) {
    asm volatile("mma.sync.aligned.m16n8k16.row.col.f32.bf16.bf16.f32 "
                 "{%0,%1,%2,%3}, {%4,%5,%6,%7}, {%8,%9}, {%0,%1,%2,%3};"
                 : "+f"(d[0]), "+f"(d[1]), "+f"(d[2]), "+f"(d[3])
                 : "r"(a[0]), "r"(a[1]), "r"(a[2]), "r"(a[3]), "r"(b0), "r"(b1));
}
__device__ __forceinline__ u32 ord(u32 fb) {
    return fb ^ ((fb & 0x80000000u) ? 0xFFFFFFFFu : 0x80000000u);
}
__device__ __forceinline__ float dec(u32 o) {
    return __uint_as_float((o & 0x80000000u) ? (o ^ 0x80000000u) : ~o);
}
__device__ __forceinline__ void upd(u64& m1, u64& m2, u64 key) {
    if (key < m1) { m2 = m1; m1 = key; } else if (key < m2) { m2 = key; }
}
__device__ __forceinline__ void merge2(u64& m1, u64& m2, u64 q1, u64 q2) {
    u64 lo = m1 < q1 ? m1 : q1;
    u64 hi = m1 < q1 ? q1 : m1;
    u64 s2 = m2 < q2 ? m2 : q2;
    m1 = lo; m2 = hi < s2 ? hi : s2;
}

__global__ void vq_transpose_kernel(const float* __restrict__ cb) {
    int i = blockIdx.x * blockDim.x + threadIdx.x;   // 0..32767
    int c = i >> 9, k = i & 511;
    g_cbT[i] = cb[k * CDIM + c];                     // bit-exact copy
}

extern __shared__ char smc[];

__global__ __launch_bounds__(THREADS, 2)
void vq_main_kernel(const float* __restrict__ x,
                    const float* __restrict__ cb,
                    float* __restrict__ out,
                    int loss_idx) {
    const u32 sb   = smem_u32(smc);
    const int tid  = threadIdx.x;
    const int w    = tid >> 5;
    const int lane = tid & 31;

    float* e2s = (float*)(smc + OFF_E2);
    float* Zs  = (float*)(smc + OFF_ZS);
    u32*   kbs = (u32*)(smc + OFF_KB);
    u32*   fls = (u32*)(smc + OFF_FL);

    const int b   = blockIdx.x >> 5;
    const int hw0 = (blockIdx.x & 31) * P_CTA;
    const float* xrow = x + (size_t)b * CDIM * HW + hw0;

    // ---- A tiles: a = -2z split to bf16 hi/lo, row p, SW128 128B rows ----
    for (int idx = tid; idx < CDIM * P_CTA; idx += THREADS) {
        int c = idx >> 7, p = idx & 127;
        float v = xrow[(size_t)c * HW + p];
        float a = -2.0f * v;                                  // exact
        __nv_bfloat16 a1 = __float2bfloat16_rn(a);
        __nv_bfloat16 a2 = __float2bfloat16_rn(__fadd_rn(a, -__bfloat162float(a1)));
        u32 o = SW((u32)(p * 128 + c * 2));
        *(__nv_bfloat16*)(smc + OFF_A(0) + o) = a1;
        *(__nv_bfloat16*)(smc + OFF_A(1) + o) = a2;
    }
    // ---- ||e_k||^2 (ref order) and Z per row (ref order) ----
    for (int k = tid; k < KCODES; k += THREADS) {
        const float* ek = cb + k * CDIM;
        float s = 0.0f;
        #pragma unroll
        for (int c = 0; c < CDIM; c++) s = __fadd_rn(s, __fmul_rn(ek[c], ek[c]));
        e2s[k] = s;
    }
    if (tid < P_CTA) {
        float s = 0.0f;
        #pragma unroll
        for (int c = 0; c < CDIM; c++) {
            float zv = xrow[(size_t)c * HW + tid];
            s = __fadd_rn(s, __fmul_rn(zv, zv));
        }
        Zs[tid] = s;
    }
    __syncthreads();

    // ---- A fragments: 2 halves x 4 k-steps (persist across B halves) ----
    const int m_base = w * 16;
    const int g      = lane >> 2;
    const int t4     = lane & 3;
    u32 afr[2][4][4];
    {
        int a_r = lane & 15, a_c8 = (lane >> 4) << 3;
        u32 xm  = (u32)((a_r & 7) << 4);
        #pragma unroll
        for (int h = 0; h < 2; h++) {
            u32 lin = sb + OFF_A(h) + (u32)((m_base + a_r) * 128 + a_c8 * 2);
            #pragma unroll
            for (int ks = 0; ks < 4; ks++)
                ldsm4((lin + ks * 32) ^ xm,
                      afr[h][ks][0], afr[h][ks][1], afr[h][ks][2], afr[h][ks][3]);
        }
    }

    const int b_r = (lane & 7) + ((lane >> 4) << 3);
    const int b_c = ((lane >> 3) & 1) << 3;
    const u32 bxm  = (u32)((b_r & 7) << 4);

    u64 mA1 = ~0ull, mA2 = ~0ull;       // row m_base+g
    u64 mB1 = ~0ull, mB2 = ~0ull;       // row m_base+g+8

    #pragma unroll 1
    for (int kh = 0; kh < 2; kh++) {
        if (kh) __syncthreads();        // previous half fully consumed
        // ---- fill B1/B2 half tiles (256 codewords), SW128 ----
        const float* cbh = cb + kh * KHALF * CDIM;
        for (int idx = tid; idx < KHALF * CDIM; idx += THREADS) {
            int k = idx >> 6, c = idx & 63;
            float e = cbh[idx];
            __nv_bfloat16 e1 = __float2bfloat16_rn(e);
            __nv_bfloat16 e2 = __float2bfloat16_rn(__fadd_rn(e, -__bfloat162float(e1)));
            u32 o = SW((u32)(k * 128 + c * 2));
            *(__nv_bfloat16*)(smc + OFF_B1 + o) = e1;
            *(__nv_bfloat16*)(smc + OFF_B2 + o) = e2;
        }
        __syncthreads();

        const u32 blin1 = sb + OFF_B1 + (u32)(b_r * 128 + b_c * 2);
        const u32 blin2 = sb + OFF_B2 + (u32)(b_r * 128 + b_c * 2);

        #pragma unroll 1
        for (int nc = 0; nc < 8; nc++) {     // 32 codewords per chunk
            float acc[4][4];
            #pragma unroll
            for (int i = 0; i < 4; i++)
                #pragma unroll
                for (int j = 0; j < 4; j++) acc[i][j] = 0.0f;

            #pragma unroll
            for (int ks = 0; ks < 4; ks++) {
                #pragma unroll
                for (int pr = 0; pr < 2; pr++) {
                    u32 off = (u32)(nc * 4096 + pr * 2048 + ks * 32);
                    u32 c0, c1, c2, c3, d0, d1, d2, d3;
                    ldsm4((blin1 + off) ^ bxm, c0, c1, c2, c3);
                    ldsm4((blin2 + off) ^ bxm, d0, d1, d2, d3);
                    mma_bf16(acc[2 * pr],     afr[0][ks], c0, c1);  // a1.e1
                    mma_bf16(acc[2 * pr],     afr[1][ks], c0, c1);  // a2.e1
                    mma_bf16(acc[2 * pr],     afr[0][ks], d0, d1);  // a1.e2
                    mma_bf16(acc[2 * pr + 1], afr[0][ks], c2, c3);
                    mma_bf16(acc[2 * pr + 1], afr[1][ks], c2, c3);
                    mma_bf16(acc[2 * pr + 1], afr[0][ks], d2, d3);
                }
            }
            #pragma unroll
            for (int nt = 0; nt < 4; nt++) {
                int col0 = kh * KHALF + nc * 32 + nt * 8 + 2 * t4;
                float e20 = e2s[col0], e21 = e2s[col0 + 1];
                float s0 = acc[nt][0] + e20;
                float s1 = acc[nt][1] + e21;
                float s2 = acc[nt][2] + e20;
                float s3 = acc[nt][3] + e21;
                upd(mA1, mA2, ((u64)ord(__float_as_uint(s0)) << 32) | (u32)col0);
                upd(mA1, mA2, ((u64)ord(__float_as_uint(s1)) << 32) | (u32)(col0 + 1));
                upd(mB1, mB2, ((u64)ord(__float_as_uint(s2)) << 32) | (u32)col0);
                upd(mB1, mB2, ((u64)ord(__float_as_uint(s3)) << 32) | (u32)(col0 + 1));
            }
        }
    }

    #pragma unroll
    for (int o = 1; o <= 2; o <<= 1) {
        merge2(mA1, mA2, __shfl_xor_sync(0xffffffffu, mA1, o),
                         __shfl_xor_sync(0xffffffffu, mA2, o));
        merge2(mB1, mB2, __shfl_xor_sync(0xffffffffu, mB1, o),
                         __shfl_xor_sync(0xffffffffu, mB2, o));
    }
    if (t4 == 0) {
        int r0 = m_base + g, r1 = m_base + g + 8;
        kbs[r0] = (u32)(mA1 & 0x1FFu);
        kbs[r1] = (u32)(mB1 & 0x1FFu);
        fls[r0] = (dec((u32)(mA2 >> 32)) - dec((u32)(mA1 >> 32))) < MARGIN;
        fls[r1] = (dec((u32)(mB2 >> 32)) - dec((u32)(mB1 >> 32))) < MARGIN;
    }
    __syncwarp();

    // ---- exact rescore of flagged rows: coalesced via g_cbT[c][k] ----
    for (int r = 0; r < 16; r++) {
        int row = m_base + r;
        if (!fls[row]) continue;
        const float* xz = xrow + row;
        float Zp = Zs[row];
        u64 best = ~0ull;
        #pragma unroll 1
        for (int jj = 0; jj < 4; jj++) {
            int k0 = lane + 128 * jj;                 // + 0,32,64,96 below
            float m0 = 0.f, m1 = 0.f, m2 = 0.f, m3 = 0.f;
            #pragma unroll
            for (int c = 0; c < CDIM; c++) {          // c ascending per chain
                float zc = __ldg(xz + (size_t)c * HW);
                const float* ct = g_cbT + c * KCODES + k0;
                m0 = __fmaf_rn(zc, __ldg(ct),      m0);   // lanes consecutive k
                m1 = __fmaf_rn(zc, __ldg(ct + 32), m1);
                m2 = __fmaf_rn(zc, __ldg(ct + 64), m2);
                m3 = __fmaf_rn(zc, __ldg(ct + 96), m3);
            }
            float mm[4] = { m0, m1, m2, m3 };
            #pragma unroll
            for (int i = 0; i < 4; i++) {
                int k = k0 + 32 * i;
                float tt = __fadd_rn(Zp, e2s[k]);
                float d  = __fadd_rn(tt, -2.0f * mm[i]);
                u64 key = ((u64)__float_as_uint(d) << 32) | (u32)k;   // d > 0
                if (key < best) best = key;
            }
        }
        #pragma unroll
        for (int o = 16; o; o >>= 1) {
            u64 v = __shfl_xor_sync(0xffffffffu, best, o);
            if (v < best) best = v;
        }
        if (lane == 0) kbs[row] = (u32)(best & 0x1FFu);
    }
    __syncthreads();

    // ---- writeback: straight-through RN(x + RN(q-x)) + SSE ----
    {
        int p = tid & 127, ch = tid >> 7;
        u32 kb = kbs[p];
        const float* qk = cb + (size_t)kb * CDIM;
        float* op = out + (size_t)b * CDIM * HW + hw0 + p;
        const float* ip = xrow + p;
        float sse = 0.0f;
        #pragma unroll 8
        for (int c = ch * 32; c < ch * 32 + 32; c++) {
            float zv   = __ldg(ip + (size_t)c * HW);
            float qv   = __ldg(qk + c);
            float diff = __fadd_rn(qv, -zv);
            op[(size_t)c * HW] = __fadd_rn(zv, diff);
            sse = __fadd_rn(sse, __fmul_rn(diff, diff));
        }
        #pragma unroll
        for (int o = 16; o; o >>= 1) sse += __shfl_xor_sync(0xffffffffu, sse, o);
        if (lane == 0) atomicAdd(&g_loss_sum, sse);
    }

    // ---- fused finalize, reset for next graph replay ----
    __syncthreads();
    if (tid == 0) {
        __threadfence();
        u32 done = atomicAdd(&g_done, 1u);
        if (done == gridDim.x - 1) {
            float L = atomicAdd(&g_loss_sum, 0.0f) * (1.0f / (float)NELEM);
            if (loss_idx >= 0)
                out[loss_idx] = __fadd_rn(L, 0.25f * L);
            g_loss_sum = 0.0f;
            g_done     = 0u;
            __threadfence();
        }
    }
}

extern "C" void kernel_launch(void* const* d_in, const int* in_sizes, int n_in,
                              void* d_out, int out_size) {
    const float* x   = (const float*)d_in[0];
    const float* cb  = (const float*)d_in[1];
    float*       out = (float*)d_out;

    cudaFuncSetAttribute(vq_main_kernel,
                         cudaFuncAttributeMaxDynamicSharedMemorySize, SMEM_SZ);
    int loss_idx = (out_size > NELEM) ? (out_size - 1) : -1;
    vq_transpose_kernel<<<CDIM * KCODES / THREADS, THREADS>>>(cb);
    vq_main_kernel<<<GRIDSZ, THREADS, SMEM_SZ>>>(x, cb, out, loss_idx);
}

// round 11
// speedup vs baseline: 7.7027x; 1.1323x over previous
#include <cuda_runtime.h>
#include <cuda_bf16.h>
#include <cstdint>

// VQ-VAE bottleneck — 3-pass split-bf16 HMMA distance GEMM + exact rescore.
// Round 11 = round 10 (passed, 315us) minus its two measured overheads:
//   (1) writeback codeword gather was 32-way uncoalesced (~60us): winners are
//       now staged into smem (reusing the dead B-tile region, 65-float pitch).
//   (2) epilogue two-min tracking was ~10 ALU ops/value via u64 keys: now the
//       9-bit k is embedded in the low mantissa bits of s and (min1,min2) are
//       tracked with 3 FMNMX/value. Embed perturbs s by <6e-6 -> MARGIN 8e-5.
//       Ties/near-ties fall inside the margin and are resolved by the exact
//       rescore, so fminf tie direction is irrelevant.
// Flagged rows rescore ALL 512 k bit-exactly (coalesced via g_cbT):
//   d = RN(RN(Z+B_k) - 2*seqFMA(z,e_k)), (d,k)-lex min (validated r2-r10).
// Output: straight-through RN(x + RN(q-x)); loss = RN(L + RN(0.25L)), L = SSE/N.

#define CDIM    64
#define KCODES  512
#define HW      4096
#define NELEM   8388608
#define THREADS 256
#define P_CTA   128
#define GRIDSZ  1024
#define MARGIN  8e-5f
#define KHALF   256
#define QPITCH  65         // staged-codeword row pitch (floats): conflict-free

typedef unsigned long long u64;
typedef unsigned int u32;

__device__ float g_loss_sum;
__device__ u32   g_done;
__device__ float g_cbT[CDIM * KCODES];   // transposed codebook [c][k]

// smem layout (bytes); tiles use SW128 swizzle on 128B rows
#define OFF_B1   0          // 256 x 128B (bf16 hi of e, current half); later qsm
#define OFF_B2   32768      // 256 x 128B (bf16 lo of e, current half)
#define OFF_A(h) (65536 + (h) * 16384)   // 2 x 128 x 128B (bf16 hi/lo of -2z)
#define OFF_E2   98304      // 512 f32  ||e_k||^2 (ref rounding)
#define OFF_ZS   100352     // 128 f32  Z per row (ref rounding)
#define OFF_KB   100864     // 128 u32  kbest
#define OFF_FL   101376     // 128 u32  flags
#define SMEM_SZ  101888
// staged winners qsm = (float*)(smc + OFF_B1): 128 * 65 * 4 = 33280 B < 64KB

#define SW(o) ((o) ^ (((o) >> 3) & 0x70))

__device__ __forceinline__ u32 smem_u32(const void* p) {
    u32 a; asm("{ .reg .u64 t; cvta.to.shared.u64 t, %1; cvt.u32.u64 %0, t; }" : "=r"(a) : "l"(p));
    return a;
}
__device__ __forceinline__ void ldsm4(u32 addr, u32& r0, u32& r1, u32& r2, u32& r3) {
    asm volatile("ldmatrix.sync.aligned.m8n8.x4.shared.b16 {%0,%1,%2,%3}, [%4];"
                 : "=r"(r0), "=r"(r1), "=r"(r2), "=r"(r3) : "r"(addr));
}
__device__ __forceinline__ void mma_bf16(float* d, const u32* a, u32 b0, u32 b1) {
    asm volatile("mma.sync.aligned.m16n8k16.row.col.f32.bf16.bf16.f32 "
                 "{%0,%1,%2,%3}, {%4,%5,%6,%7}, {%8,%9}, {%0,%1,%2,%3};"
                 : "+f"(d[0]), "+f"(d[1]), "+f"(d[2]), "+f"(d[3])
                 : "r"(a[0]), "r"(a[1]), "r"(a[2]), "r"(a[3]), "r"(b0), "r"(b1));
}
// embed k (9 bits) into low mantissa bits of s
__device__ __forceinline__ float embed(float s, int k) {
    return __uint_as_float((__float_as_uint(s) & ~511u) | (u32)k);
}
// two-min update: 3 FMNMX
__device__ __forceinline__ void upd2(float& m1, float& m2, float v) {
    float hi = fmaxf(m1, v);
    m1 = fminf(m1, v);
    m2 = fminf(m2, hi);
}

__global__ void vq_transpose_kernel(const float* __restrict__ cb) {
    int i = blockIdx.x * blockDim.x + threadIdx.x;   // 0..32767
    int c = i >> 9, k = i & 511;
    g_cbT[i] = cb[k * CDIM + c];                     // bit-exact copy
}

extern __shared__ char smc[];

__global__ __launch_bounds__(THREADS, 2)
void vq_main_kernel(const float* __restrict__ x,
                    const float* __restrict__ cb,
                    float* __restrict__ out,
                    int loss_idx) {
    const u32 sb   = smem_u32(smc);
    const int tid  = threadIdx.x;
    const int w    = tid >> 5;
    const int lane = tid & 31;

    float* e2s = (float*)(smc + OFF_E2);
    float* Zs  = (float*)(smc + OFF_ZS);
    u32*   kbs = (u32*)(smc + OFF_KB);
    u32*   fls = (u32*)(smc + OFF_FL);
    float* qsm = (float*)(smc + OFF_B1);     // valid after mainloop

    const int b   = blockIdx.x >> 5;
    const int hw0 = (blockIdx.x & 31) * P_CTA;
    const float* xrow = x + (size_t)b * CDIM * HW + hw0;

    // ---- A tiles: a = -2z split to bf16 hi/lo, row p, SW128 128B rows ----
    for (int idx = tid; idx < CDIM * P_CTA; idx += THREADS) {
        int c = idx >> 7, p = idx & 127;
        float v = xrow[(size_t)c * HW + p];
        float a = -2.0f * v;                                  // exact
        __nv_bfloat16 a1 = __float2bfloat16_rn(a);
        __nv_bfloat16 a2 = __float2bfloat16_rn(__fadd_rn(a, -__bfloat162float(a1)));
        u32 o = SW((u32)(p * 128 + c * 2));
        *(__nv_bfloat16*)(smc + OFF_A(0) + o) = a1;
        *(__nv_bfloat16*)(smc + OFF_A(1) + o) = a2;
    }
    // ---- ||e_k||^2 (ref order) and Z per row (ref order) ----
    for (int k = tid; k < KCODES; k += THREADS) {
        const float* ek = cb + k * CDIM;
        float s = 0.0f;
        #pragma unroll
        for (int c = 0; c < CDIM; c++) s = __fadd_rn(s, __fmul_rn(ek[c], ek[c]));
        e2s[k] = s;
    }
    if (tid < P_CTA) {
        float s = 0.0f;
        #pragma unroll
        for (int c = 0; c < CDIM; c++) {
            float zv = xrow[(size_t)c * HW + tid];
            s = __fadd_rn(s, __fmul_rn(zv, zv));
        }
        Zs[tid] = s;
    }
    __syncthreads();

    // ---- A fragments: 2 halves x 4 k-steps (persist across B halves) ----
    const int m_base = w * 16;
    const int g      = lane >> 2;
    const int t4     = lane & 3;
    u32 afr[2][4][4];
    {
        int a_r = lane & 15, a_c8 = (lane >> 4) << 3;
        u32 xm  = (u32)((a_r & 7) << 4);
        #pragma unroll
        for (int h = 0; h < 2; h++) {
            u32 lin = sb + OFF_A(h) + (u32)((m_base + a_r) * 128 + a_c8 * 2);
            #pragma unroll
            for (int ks = 0; ks < 4; ks++)
                ldsm4((lin + ks * 32) ^ xm,
                      afr[h][ks][0], afr[h][ks][1], afr[h][ks][2], afr[h][ks][3]);
        }
    }

    const int b_r = (lane & 7) + ((lane >> 4) << 3);
    const int b_c = ((lane >> 3) & 1) << 3;
    const u32 bxm  = (u32)((b_r & 7) << 4);

    float mA1 = 1e30f, mA2 = 1e30f;      // row m_base+g   (embedded s values)
    float mB1 = 1e30f, mB2 = 1e30f;      // row m_base+g+8

    #pragma unroll 1
    for (int kh = 0; kh < 2; kh++) {
        if (kh) __syncthreads();         // previous half fully consumed
        // ---- fill B1/B2 half tiles (256 codewords), SW128 ----
        const float* cbh = cb + kh * KHALF * CDIM;
        for (int idx = tid; idx < KHALF * CDIM; idx += THREADS) {
            int k = idx >> 6, c = idx & 63;
            float e = cbh[idx];
            __nv_bfloat16 e1 = __float2bfloat16_rn(e);
            __nv_bfloat16 e2 = __float2bfloat16_rn(__fadd_rn(e, -__bfloat162float(e1)));
            u32 o = SW((u32)(k * 128 + c * 2));
            *(__nv_bfloat16*)(smc + OFF_B1 + o) = e1;
            *(__nv_bfloat16*)(smc + OFF_B2 + o) = e2;
        }
        __syncthreads();

        const u32 blin1 = sb + OFF_B1 + (u32)(b_r * 128 + b_c * 2);
        const u32 blin2 = sb + OFF_B2 + (u32)(b_r * 128 + b_c * 2);

        #pragma unroll 1
        for (int nc = 0; nc < 8; nc++) {     // 32 codewords per chunk
            float acc[4][4];
            #pragma unroll
            for (int i = 0; i < 4; i++)
                #pragma unroll
                for (int j = 0; j < 4; j++) acc[i][j] = 0.0f;

            #pragma unroll
            for (int ks = 0; ks < 4; ks++) {
                #pragma unroll
                for (int pr = 0; pr < 2; pr++) {
                    u32 off = (u32)(nc * 4096 + pr * 2048 + ks * 32);
                    u32 c0, c1, c2, c3, d0, d1, d2, d3;
                    ldsm4((blin1 + off) ^ bxm, c0, c1, c2, c3);
                    ldsm4((blin2 + off) ^ bxm, d0, d1, d2, d3);
                    mma_bf16(acc[2 * pr],     afr[0][ks], c0, c1);  // a1.e1
                    mma_bf16(acc[2 * pr],     afr[1][ks], c0, c1);  // a2.e1
                    mma_bf16(acc[2 * pr],     afr[0][ks], d0, d1);  // a1.e2
                    mma_bf16(acc[2 * pr + 1], afr[0][ks], c2, c3);
                    mma_bf16(acc[2 * pr + 1], afr[1][ks], c2, c3);
                    mma_bf16(acc[2 * pr + 1], afr[0][ks], d2, d3);
                }
            }
            #pragma unroll
            for (int nt = 0; nt < 4; nt++) {
                int col0 = kh * KHALF + nc * 32 + nt * 8 + 2 * t4;
                float e20 = e2s[col0], e21 = e2s[col0 + 1];
                upd2(mA1, mA2, embed(acc[nt][0] + e20, col0));
                upd2(mA1, mA2, embed(acc[nt][1] + e21, col0 + 1));
                upd2(mB1, mB2, embed(acc[nt][2] + e20, col0));
                upd2(mB1, mB2, embed(acc[nt][3] + e21, col0 + 1));
            }
        }
    }

    // quad reduce (lanes share a row across t4)
    #pragma unroll
    for (int o = 1; o <= 2; o <<= 1) {
        float a1 = __shfl_xor_sync(0xffffffffu, mA1, o);
        float a2 = __shfl_xor_sync(0xffffffffu, mA2, o);
        float hA = fmaxf(mA1, a1);
        mA1 = fminf(mA1, a1);
        mA2 = fminf(fminf(mA2, a2), hA);
        float b1 = __shfl_xor_sync(0xffffffffu, mB1, o);
        float b2 = __shfl_xor_sync(0xffffffffu, mB2, o);
        float hB = fmaxf(mB1, b1);
        mB1 = fminf(mB1, b1);
        mB2 = fminf(fminf(mB2, b2), hB);
    }
    if (t4 == 0) {
        int r0 = m_base + g, r1 = m_base + g + 8;
        kbs[r0] = __float_as_uint(mA1) & 511u;
        kbs[r1] = __float_as_uint(mB1) & 511u;
        fls[r0] = (mA2 - mA1) < MARGIN;
        fls[r1] = (mB2 - mB1) < MARGIN;
    }
    __syncwarp();

    // ---- exact rescore of flagged rows: coalesced via g_cbT[c][k] ----
    for (int r = 0; r < 16; r++) {
        int row = m_base + r;
        if (!fls[row]) continue;
        const float* xz = xrow + row;
        float Zp = Zs[row];
        u64 best = ~0ull;
        #pragma unroll 1
        for (int jj = 0; jj < 4; jj++) {
            int k0 = lane + 128 * jj;                 // + 0,32,64,96 below
            float m0 = 0.f, m1 = 0.f, m2 = 0.f, m3 = 0.f;
            #pragma unroll
            for (int c = 0; c < CDIM; c++) {          // c ascending per chain
                float zc = __ldg(xz + (size_t)c * HW);
                const float* ct = g_cbT + c * KCODES + k0;
                m0 = __fmaf_rn(zc, __ldg(ct),      m0);   // lanes consecutive k
                m1 = __fmaf_rn(zc, __ldg(ct + 32), m1);
                m2 = __fmaf_rn(zc, __ldg(ct + 64), m2);
                m3 = __fmaf_rn(zc, __ldg(ct + 96), m3);
            }
            float mm[4] = { m0, m1, m2, m3 };
            #pragma unroll
            for (int i = 0; i < 4; i++) {
                int k = k0 + 32 * i;
                float tt = __fadd_rn(Zp, e2s[k]);
                float d  = __fadd_rn(tt, -2.0f * mm[i]);
                u64 key = ((u64)__float_as_uint(d) << 32) | (u32)k;   // d > 0
                if (key < best) best = key;
            }
        }
        #pragma unroll
        for (int o = 16; o; o >>= 1) {
            u64 v = __shfl_xor_sync(0xffffffffu, best, o);
            if (v < best) best = v;
        }
        if (lane == 0) kbs[row] = (u32)(best & 0x1FFu);
    }
    __syncthreads();   // kbs final; B tiles dead -> qsm may overwrite

    // ---- stage winning codewords into smem, coalesced ----
    // warp w loads rows [16w,16w+16); per row, lanes read 64 consecutive floats
    for (int i = 0; i < 16; i++) {
        int row = m_base + i;
        const float* src = cb + (size_t)kbs[row] * CDIM;
        qsm[row * QPITCH + lane]      = __ldg(src + lane);
        qsm[row * QPITCH + lane + 32] = __ldg(src + lane + 32);
    }
    __syncthreads();

    // ---- writeback: straight-through RN(x + RN(q-x)) + SSE, q from smem ----
    {
        int p = tid & 127, ch = tid >> 7;
        float* op = out + (size_t)b * CDIM * HW + hw0 + p;
        const float* ip = xrow + p;
        const float* qp = qsm + p * QPITCH;
        float sse = 0.0f;
        #pragma unroll 8
        for (int c = ch * 32; c < ch * 32 + 32; c++) {
            float zv   = __ldg(ip + (size_t)c * HW);
            float qv   = qp[c];                        // LDS, conflict-free
            float diff = __fadd_rn(qv, -zv);
            op[(size_t)c * HW] = __fadd_rn(zv, diff);
            sse = __fadd_rn(sse, __fmul_rn(diff, diff));
        }
        #pragma unroll
        for (int o = 16; o; o >>= 1) sse += __shfl_xor_sync(0xffffffffu, sse, o);
        if (lane == 0) atomicAdd(&g_loss_sum, sse);
    }

    // ---- fused finalize, reset for next graph replay ----
    __syncthreads();
    if (tid == 0) {
        __threadfence();
        u32 done = atomicAdd(&g_done, 1u);
        if (done == gridDim.x - 1) {
            float L = atomicAdd(&g_loss_sum, 0.0f) * (1.0f / (float)NELEM);
            if (loss_idx >= 0)
                out[loss_idx] = __fadd_rn(L, 0.25f * L);
            g_loss_sum = 0.0f;
            g_done     = 0u;
            __threadfence();
        }
    }
}

extern "C" void kernel_launch(void* const* d_in, const int* in_sizes, int n_in,
                              void* d_out, int out_size) {
    const float* x   = (const float*)d_in[0];
    const float* cb  = (const float*)d_in[1];
    float*       out = (float*)d_out;

    cudaFuncSetAttribute(vq_main_kernel,
                         cudaFuncAttributeMaxDynamicSharedMemorySize, SMEM_SZ);
    int loss_idx = (out_size > NELEM) ? (out_size - 1) : -1;
    vq_transpose_kernel<<<CDIM * KCODES / THREADS, THREADS>>>(cb);
    vq_main_kernel<<<GRIDSZ, THREADS, SMEM_SZ>>>(x, cb, out, loss_idx);
}

// round 12
// speedup vs baseline: 13.9028x; 1.8049x over previous
#include <cuda_runtime.h>
#include <cuda_bf16.h>
#include <cstdint>

// VQ-VAE bottleneck — 3-pass split-bf16 HMMA distance GEMM + exact rescore.
// Round 12 = round 11 (passed, 279us) with position-independent work hoisted
// into a prep kernel (ncu showed L1 58% / alu 14.5%, dominated by every CTA
// recomputing ||e_k||^2 with lane-strided reads and re-converting the codebook
// to split-bf16):
//   prep: g_e2[512] (ref-order ||e||^2), g_cbB1/g_cbB2 (split-bf16 codebook
//         PRE-SWIZZLED in smem byte layout -> main fill is a uint4 memcpy),
//         g_cbT (fp32 transpose for coalesced rescore).
// All numerics bit-identical to r11 (validated r2-r11):
//   flagged rows (gap < MARGIN) rescore all 512 k exactly:
//   d = RN(RN(Z+B_k) - 2*seqFMA(z,e_k)), (d,k)-lex min.
// Output: straight-through RN(x + RN(q-x)); loss = RN(L + RN(0.25L)), L = SSE/N.

#define CDIM    64
#define KCODES  512
#define HW      4096
#define NELEM   8388608
#define THREADS 256
#define P_CTA   128
#define GRIDSZ  1024
#define MARGIN  8e-5f
#define KHALF   256
#define QPITCH  65

typedef unsigned long long u64;
typedef unsigned int u32;
typedef unsigned short u16;

__device__ float g_loss_sum;
__device__ u32   g_done;
__device__ float g_cbT[CDIM * KCODES];    // transposed codebook [c][k]
__device__ float g_e2[KCODES];            // ||e_k||^2, reference rounding
__device__ uint4 g_cbB1[4096];            // 64KB split-bf16 hi, SW128 layout
__device__ uint4 g_cbB2[4096];            // 64KB split-bf16 lo, SW128 layout

// smem layout (bytes); tiles use SW128 swizzle on 128B rows
#define OFF_B1   0          // 256 x 128B (current half, bf16 hi); later qsm
#define OFF_B2   32768      // 256 x 128B (current half, bf16 lo)
#define OFF_A(h) (65536 + (h) * 16384)   // 2 x 128 x 128B (bf16 hi/lo of -2z)
#define OFF_E2   98304      // 512 f32
#define OFF_ZS   100352     // 128 f32
#define OFF_KB   100864     // 128 u32
#define OFF_FL   101376     // 128 u32
#define SMEM_SZ  101888

#define SW(o) ((o) ^ (((o) >> 3) & 0x70))

__device__ __forceinline__ u32 smem_u32(const void* p) {
    u32 a; asm("{ .reg .u64 t; cvta.to.shared.u64 t, %1; cvt.u32.u64 %0, t; }" : "=r"(a) : "l"(p));
    return a;
}
__device__ __forceinline__ void ldsm4(u32 addr, u32& r0, u32& r1, u32& r2, u32& r3) {
    asm volatile("ldmatrix.sync.aligned.m8n8.x4.shared.b16 {%0,%1,%2,%3}, [%4];"
                 : "=r"(r0), "=r"(r1), "=r"(r2), "=r"(r3) : "r"(addr));
}
__device__ __forceinline__ void mma_bf16(float* d, const u32* a, u32 b0, u32 b1) {
    asm volatile("mma.sync.aligned.m16n8k16.row.col.f32.bf16.bf16.f32 "
                 "{%0,%1,%2,%3}, {%4,%5,%6,%7}, {%8,%9}, {%0,%1,%2,%3};"
                 : "+f"(d[0]), "+f"(d[1]), "+f"(d[2]), "+f"(d[3])
                 : "r"(a[0]), "r"(a[1]), "r"(a[2]), "r"(a[3]), "r"(b0), "r"(b1));
}
__device__ __forceinline__ float embed(float s, int k) {
    return __uint_as_float((__float_as_uint(s) & ~511u) | (u32)k);
}
__device__ __forceinline__ void upd2(float& m1, float& m2, float v) {
    float hi = fmaxf(m1, v);
    m1 = fminf(m1, v);
    m2 = fminf(m2, hi);
}

// ---- prep: codebook-derived tables (once per launch/replay) ----
__global__ void vq_prep_kernel(const float* __restrict__ cb) {
    int i = blockIdx.x * blockDim.x + threadIdx.x;     // 0..32767
    int k = i >> 6, c = i & 63;
    float e = cb[i];                                    // coalesced
    g_cbT[c * KCODES + k] = e;                          // bit-exact transpose
    __nv_bfloat16 e1 = __float2bfloat16_rn(e);
    __nv_bfloat16 e2 = __float2bfloat16_rn(__fadd_rn(e, -__bfloat162float(e1)));
    u32 o = SW((u32)(k * 128 + c * 2)) >> 1;            // u16 index, smem layout
    ((u16*)g_cbB1)[o] = *(u16*)&e1;
    ((u16*)g_cbB2)[o] = *(u16*)&e2;
    if (i < KCODES) {                                   // ||e_i||^2, ref order
        const float* ek = cb + i * CDIM;
        float s = 0.0f;
        #pragma unroll
        for (int cc = 0; cc < CDIM; cc++)
            s = __fadd_rn(s, __fmul_rn(ek[cc], ek[cc]));
        g_e2[i] = s;
    }
}

extern __shared__ char smc[];

__global__ __launch_bounds__(THREADS, 2)
void vq_main_kernel(const float* __restrict__ x,
                    const float* __restrict__ cb,
                    float* __restrict__ out,
                    int loss_idx) {
    const u32 sb   = smem_u32(smc);
    const int tid  = threadIdx.x;
    const int w    = tid >> 5;
    const int lane = tid & 31;

    float* e2s = (float*)(smc + OFF_E2);
    float* Zs  = (float*)(smc + OFF_ZS);
    u32*   kbs = (u32*)(smc + OFF_KB);
    u32*   fls = (u32*)(smc + OFF_FL);
    float* qsm = (float*)(smc + OFF_B1);     // valid after mainloop

    const int b   = blockIdx.x >> 5;
    const int hw0 = (blockIdx.x & 31) * P_CTA;
    const float* xrow = x + (size_t)b * CDIM * HW + hw0;

    // ---- A tiles: a = -2z split to bf16 hi/lo, row p, SW128 128B rows ----
    for (int idx = tid; idx < CDIM * P_CTA; idx += THREADS) {
        int c = idx >> 7, p = idx & 127;
        float v = xrow[(size_t)c * HW + p];
        float a = -2.0f * v;                                  // exact
        __nv_bfloat16 a1 = __float2bfloat16_rn(a);
        __nv_bfloat16 a2 = __float2bfloat16_rn(__fadd_rn(a, -__bfloat162float(a1)));
        u32 o = SW((u32)(p * 128 + c * 2));
        *(__nv_bfloat16*)(smc + OFF_A(0) + o) = a1;
        *(__nv_bfloat16*)(smc + OFF_A(1) + o) = a2;
    }
    // ---- tables: e2 coalesced from prep; Z per row (ref order) ----
    for (int k = tid; k < KCODES; k += THREADS) e2s[k] = g_e2[k];
    if (tid < P_CTA) {
        float s = 0.0f;
        #pragma unroll
        for (int c = 0; c < CDIM; c++) {
            float zv = xrow[(size_t)c * HW + tid];
            s = __fadd_rn(s, __fmul_rn(zv, zv));
        }
        Zs[tid] = s;
    }
    __syncthreads();

    // ---- A fragments: 2 halves x 4 k-steps (persist across B halves) ----
    const int m_base = w * 16;
    const int g      = lane >> 2;
    const int t4     = lane & 3;
    u32 afr[2][4][4];
    {
        int a_r = lane & 15, a_c8 = (lane >> 4) << 3;
        u32 xm  = (u32)((a_r & 7) << 4);
        #pragma unroll
        for (int h = 0; h < 2; h++) {
            u32 lin = sb + OFF_A(h) + (u32)((m_base + a_r) * 128 + a_c8 * 2);
            #pragma unroll
            for (int ks = 0; ks < 4; ks++)
                ldsm4((lin + ks * 32) ^ xm,
                      afr[h][ks][0], afr[h][ks][1], afr[h][ks][2], afr[h][ks][3]);
        }
    }

    const int b_r = (lane & 7) + ((lane >> 4) << 3);
    const int b_c = ((lane >> 3) & 1) << 3;
    const u32 bxm  = (u32)((b_r & 7) << 4);

    float mA1 = 1e30f, mA2 = 1e30f;      // row m_base+g   (embedded s values)
    float mB1 = 1e30f, mB2 = 1e30f;      // row m_base+g+8

    #pragma unroll 1
    for (int kh = 0; kh < 2; kh++) {
        if (kh) __syncthreads();         // previous half fully consumed
        // ---- fill B1/B2 half tiles: straight uint4 copy (pre-swizzled) ----
        {
            const uint4* s1 = g_cbB1 + kh * 2048;
            const uint4* s2 = g_cbB2 + kh * 2048;
            uint4* d1 = (uint4*)(smc + OFF_B1);
            uint4* d2 = (uint4*)(smc + OFF_B2);
            #pragma unroll
            for (int i = tid; i < 2048; i += THREADS) {
                d1[i] = s1[i];
                d2[i] = s2[i];
            }
        }
        __syncthreads();

        const u32 blin1 = sb + OFF_B1 + (u32)(b_r * 128 + b_c * 2);
        const u32 blin2 = sb + OFF_B2 + (u32)(b_r * 128 + b_c * 2);

        #pragma unroll 1
        for (int nc = 0; nc < 8; nc++) {     // 32 codewords per chunk
            float acc[4][4];
            #pragma unroll
            for (int i = 0; i < 4; i++)
                #pragma unroll
                for (int j = 0; j < 4; j++) acc[i][j] = 0.0f;

            #pragma unroll
            for (int ks = 0; ks < 4; ks++) {
                #pragma unroll
                for (int pr = 0; pr < 2; pr++) {
                    u32 off = (u32)(nc * 4096 + pr * 2048 + ks * 32);
                    u32 c0, c1, c2, c3, d0, d1, d2, d3;
                    ldsm4((blin1 + off) ^ bxm, c0, c1, c2, c3);
                    ldsm4((blin2 + off) ^ bxm, d0, d1, d2, d3);
                    mma_bf16(acc[2 * pr],     afr[0][ks], c0, c1);  // a1.e1
                    mma_bf16(acc[2 * pr],     afr[1][ks], c0, c1);  // a2.e1
                    mma_bf16(acc[2 * pr],     afr[0][ks], d0, d1);  // a1.e2
                    mma_bf16(acc[2 * pr + 1], afr[0][ks], c2, c3);
                    mma_bf16(acc[2 * pr + 1], afr[1][ks], c2, c3);
                    mma_bf16(acc[2 * pr + 1], afr[0][ks], d2, d3);
                }
            }
            #pragma unroll
            for (int nt = 0; nt < 4; nt++) {
                int col0 = kh * KHALF + nc * 32 + nt * 8 + 2 * t4;
                float e20 = e2s[col0], e21 = e2s[col0 + 1];
                upd2(mA1, mA2, embed(acc[nt][0] + e20, col0));
                upd2(mA1, mA2, embed(acc[nt][1] + e21, col0 + 1));
                upd2(mB1, mB2, embed(acc[nt][2] + e20, col0));
                upd2(mB1, mB2, embed(acc[nt][3] + e21, col0 + 1));
            }
        }
    }

    // quad reduce (lanes share a row across t4)
    #pragma unroll
    for (int o = 1; o <= 2; o <<= 1) {
        float a1 = __shfl_xor_sync(0xffffffffu, mA1, o);
        float a2 = __shfl_xor_sync(0xffffffffu, mA2, o);
        float hA = fmaxf(mA1, a1);
        mA1 = fminf(mA1, a1);
        mA2 = fminf(fminf(mA2, a2), hA);
        float b1 = __shfl_xor_sync(0xffffffffu, mB1, o);
        float b2 = __shfl_xor_sync(0xffffffffu, mB2, o);
        float hB = fmaxf(mB1, b1);
        mB1 = fminf(mB1, b1);
        mB2 = fminf(fminf(mB2, b2), hB);
    }
    if (t4 == 0) {
        int r0 = m_base + g, r1 = m_base + g + 8;
        kbs[r0] = __float_as_uint(mA1) & 511u;
        kbs[r1] = __float_as_uint(mB1) & 511u;
        fls[r0] = (mA2 - mA1) < MARGIN;
        fls[r1] = (mB2 - mB1) < MARGIN;
    }
    __syncwarp();

    // ---- exact rescore of flagged rows: coalesced via g_cbT[c][k] ----
    for (int r = 0; r < 16; r++) {
        int row = m_base + r;
        if (!fls[row]) continue;
        const float* xz = xrow + row;
        float Zp = Zs[row];
        u64 best = ~0ull;
        #pragma unroll 1
        for (int jj = 0; jj < 4; jj++) {
            int k0 = lane + 128 * jj;                 // + 0,32,64,96 below
            float m0 = 0.f, m1 = 0.f, m2 = 0.f, m3 = 0.f;
            #pragma unroll
            for (int c = 0; c < CDIM; c++) {          // c ascending per chain
                float zc = __ldg(xz + (size_t)c * HW);
                const float* ct = g_cbT + c * KCODES + k0;
                m0 = __fmaf_rn(zc, __ldg(ct),      m0);   // lanes consecutive k
                m1 = __fmaf_rn(zc, __ldg(ct + 32), m1);
                m2 = __fmaf_rn(zc, __ldg(ct + 64), m2);
                m3 = __fmaf_rn(zc, __ldg(ct + 96), m3);
            }
            float mm[4] = { m0, m1, m2, m3 };
            #pragma unroll
            for (int i = 0; i < 4; i++) {
                int k = k0 + 32 * i;
                float tt = __fadd_rn(Zp, e2s[k]);
                float d  = __fadd_rn(tt, -2.0f * mm[i]);
                u64 key = ((u64)__float_as_uint(d) << 32) | (u32)k;   // d > 0
                if (key < best) best = key;
            }
        }
        #pragma unroll
        for (int o = 16; o; o >>= 1) {
            u64 v = __shfl_xor_sync(0xffffffffu, best, o);
            if (v < best) best = v;
        }
        if (lane == 0) kbs[row] = (u32)(best & 0x1FFu);
    }
    __syncthreads();   // kbs final; B tiles dead -> qsm may overwrite

    // ---- stage winning codewords into smem, coalesced ----
    for (int i = 0; i < 16; i++) {
        int row = m_base + i;
        const float* src = cb + (size_t)kbs[row] * CDIM;
        qsm[row * QPITCH + lane]      = __ldg(src + lane);
        qsm[row * QPITCH + lane + 32] = __ldg(src + lane + 32);
    }
    __syncthreads();

    // ---- writeback: straight-through RN(x + RN(q-x)) + SSE, q from smem ----
    {
        int p = tid & 127, ch = tid >> 7;
        float* op = out + (size_t)b * CDIM * HW + hw0 + p;
        const float* ip = xrow + p;
        const float* qp = qsm + p * QPITCH;
        float sse = 0.0f;
        #pragma unroll 8
        for (int c = ch * 32; c < ch * 32 + 32; c++) {
            float zv   = __ldg(ip + (size_t)c * HW);
            float qv   = qp[c];                        // LDS, conflict-free
            float diff = __fadd_rn(qv, -zv);
            op[(size_t)c * HW] = __fadd_rn(zv, diff);
            sse = __fadd_rn(sse, __fmul_rn(diff, diff));
        }
        #pragma unroll
        for (int o = 16; o; o >>= 1) sse += __shfl_xor_sync(0xffffffffu, sse, o);
        if (lane == 0) atomicAdd(&g_loss_sum, sse);
    }

    // ---- fused finalize, reset for next graph replay ----
    __syncthreads();
    if (tid == 0) {
        __threadfence();
        u32 done = atomicAdd(&g_done, 1u);
        if (done == gridDim.x - 1) {
            float L = atomicAdd(&g_loss_sum, 0.0f) * (1.0f / (float)NELEM);
            if (loss_idx >= 0)
                out[loss_idx] = __fadd_rn(L, 0.25f * L);
            g_loss_sum = 0.0f;
            g_done     = 0u;
            __threadfence();
        }
    }
}

extern "C" void kernel_launch(void* const* d_in, const int* in_sizes, int n_in,
                              void* d_out, int out_size) {
    const float* x   = (const float*)d_in[0];
    const float* cb  = (const float*)d_in[1];
    float*       out = (float*)d_out;

    cudaFuncSetAttribute(vq_main_kernel,
                         cudaFuncAttributeMaxDynamicSharedMemorySize, SMEM_SZ);
    int loss_idx = (out_size > NELEM) ? (out_size - 1) : -1;
    vq_prep_kernel<<<128, THREADS>>>(cb);
    vq_main_kernel<<<GRIDSZ, THREADS, SMEM_SZ>>>(x, cb, out, loss_idx);
}

// round 13
// speedup vs baseline: 15.1873x; 1.0924x over previous
#include <cuda_runtime.h>
#include <cuda_fp16.h>
#include <cstdint>

// VQ-VAE bottleneck — 2-pass split-fp16 HMMA distance GEMM + exact rescore.
// Round 13 = round 12 (passed, 154us) with the mainloop slimmed:
//   bf16 3-pass (a1e1+a2e1+a1e2, 768 mma/warp) -> fp16 2-pass (a1e1+a2e1,
//   512 mma/warp). fp16's 11-bit mantissa makes a single fp16 e accurate
//   enough: dropped |a.(e-e1)| <= ||a_m|| * em, em = max_k ||e_k - fp16(e_k)||
//   computed EXACTLY in prep. Scaling (e*1024, a*16, unscale 2^-14 folded into
//   the epilogue FFMA) keeps all fp16 operands normal.
//   Per-row margin: 4*sqrt(Z)*em + 5e-5 (covers accum rounding, ref-rounding
//   slack, embed perturbation, fp16 subnormal-FTZ residue).
// Flagged rows rescore ALL 512 k bit-exactly (coalesced via g_cbT):
//   d = RN(RN(Z+B_k) - 2*seqFMA(z,e_k)), (d,k)-lex min (validated r2-r12).
// Output: straight-through RN(x + RN(q-x)); loss = RN(L + RN(0.25L)), L = SSE/N.

#define CDIM    64
#define KCODES  512
#define HW      4096
#define NELEM   8388608
#define THREADS 256
#define P_CTA   128
#define GRIDSZ  1024
#define QPITCH  65

typedef unsigned long long u64;
typedef unsigned int u32;
typedef unsigned short u16;

__device__ float g_loss_sum;
__device__ u32   g_done;
__device__ float g_cbT[CDIM * KCODES];    // transposed codebook [c][k]
__device__ float g_e2[KCODES];            // ||e_k||^2, reference rounding
__device__ u32   g_em2;                   // bits of max_k ||e_k - fp16(e_k)||^2
__device__ uint4 g_cbB1[4096];            // 64KB fp16(1024*e), SW128 smem layout

// smem layout (bytes); tiles use SW128 swizzle on 128B rows
#define OFF_B1   0          // 512 x 128B fp16 e tile; later qsm (33280B fits)
#define OFF_A(h) (65536 + (h) * 16384)   // 2 x 128 x 128B (fp16 hi/lo of -32z)
#define OFF_E2   98304      // 512 f32
#define OFF_ZS   100352     // 128 f32
#define OFF_KB   100864     // 128 u32
#define OFF_FL   101376     // 128 u32
#define SMEM_SZ  101888

#define SW(o) ((o) ^ (((o) >> 3) & 0x70))

__device__ __forceinline__ u32 smem_u32(const void* p) {
    u32 a; asm("{ .reg .u64 t; cvta.to.shared.u64 t, %1; cvt.u32.u64 %0, t; }" : "=r"(a) : "l"(p));
    return a;
}
__device__ __forceinline__ void ldsm4(u32 addr, u32& r0, u32& r1, u32& r2, u32& r3) {
    asm volatile("ldmatrix.sync.aligned.m8n8.x4.shared.b16 {%0,%1,%2,%3}, [%4];"
                 : "=r"(r0), "=r"(r1), "=r"(r2), "=r"(r3) : "r"(addr));
}
__device__ __forceinline__ void mma_f16(float* d, const u32* a, u32 b0, u32 b1) {
    asm volatile("mma.sync.aligned.m16n8k16.row.col.f32.f16.f16.f32 "
                 "{%0,%1,%2,%3}, {%4,%5,%6,%7}, {%8,%9}, {%0,%1,%2,%3};"
                 : "+f"(d[0]), "+f"(d[1]), "+f"(d[2]), "+f"(d[3])
                 : "r"(a[0]), "r"(a[1]), "r"(a[2]), "r"(a[3]), "r"(b0), "r"(b1));
}
__device__ __forceinline__ float embed(float s, int k) {
    return __uint_as_float((__float_as_uint(s) & ~511u) | (u32)k);
}
__device__ __forceinline__ void upd2(float& m1, float& m2, float v) {
    float hi = fmaxf(m1, v);
    m1 = fminf(m1, v);
    m2 = fminf(m2, hi);
}

// ---- prep: codebook-derived tables (idempotent across graph replays) ----
__global__ void vq_prep_kernel(const float* __restrict__ cb) {
    int i = blockIdx.x * blockDim.x + threadIdx.x;     // 0..32767
    int k = i >> 6, c = i & 63;
    float e = cb[i];                                    // coalesced
    g_cbT[c * KCODES + k] = e;                          // bit-exact transpose
    __half e1 = __float2half_rn(e * 1024.0f);           // scaled: all normal
    u32 o = SW((u32)(k * 128 + c * 2)) >> 1;            // u16 index, smem layout
    ((u16*)g_cbB1)[o] = *(u16*)&e1;
    if (i < KCODES) {                                   // ||e_i||^2 ref order + residual
        const float* ek = cb + i * CDIM;
        float s = 0.0f, r2 = 0.0f;
        #pragma unroll
        for (int cc = 0; cc < CDIM; cc++) {
            float ev = ek[cc];
            s = __fadd_rn(s, __fmul_rn(ev, ev));
            float eh = __half2float(__float2half_rn(ev * 1024.0f)) * 0.0009765625f;
            float r  = ev - eh;
            r2 += r * r;
        }
        g_e2[i] = s;
        atomicMax(&g_em2, __float_as_uint(r2));         // r2 >= 0: bits monotone
    }
}

extern __shared__ char smc[];

__global__ __launch_bounds__(THREADS, 2)
void vq_main_kernel(const float* __restrict__ x,
                    const float* __restrict__ cb,
                    float* __restrict__ out,
                    int loss_idx) {
    const u32 sb   = smem_u32(smc);
    const int tid  = threadIdx.x;
    const int w    = tid >> 5;
    const int lane = tid & 31;

    float* e2s = (float*)(smc + OFF_E2);
    float* Zs  = (float*)(smc + OFF_ZS);
    u32*   kbs = (u32*)(smc + OFF_KB);
    u32*   fls = (u32*)(smc + OFF_FL);
    float* qsm = (float*)(smc + OFF_B1);     // valid after mainloop

    const int b   = blockIdx.x >> 5;
    const int hw0 = (blockIdx.x & 31) * P_CTA;
    const float* xrow = x + (size_t)b * CDIM * HW + hw0;

    // ---- A tiles: a = -32z (16x scale) split to fp16 hi/lo, SW128 rows ----
    for (int idx = tid; idx < CDIM * P_CTA; idx += THREADS) {
        int c = idx >> 7, p = idx & 127;
        float v = xrow[(size_t)c * HW + p];
        float a = -32.0f * v;                                 // exact
        __half a1 = __float2half_rn(a);
        __half a2 = __float2half_rn(__fadd_rn(a, -__half2float(a1)));
        u32 o = SW((u32)(p * 128 + c * 2));
        *(__half*)(smc + OFF_A(0) + o) = a1;
        *(__half*)(smc + OFF_A(1) + o) = a2;
    }
    // ---- B tile: single 64KB pre-swizzled copy; tables; Z per row ----
    {
        const uint4* s1 = g_cbB1;
        uint4* d1 = (uint4*)(smc + OFF_B1);
        #pragma unroll
        for (int i = tid; i < 4096; i += THREADS) d1[i] = s1[i];
    }
    for (int k = tid; k < KCODES; k += THREADS) e2s[k] = g_e2[k];
    if (tid < P_CTA) {
        float s = 0.0f;
        #pragma unroll
        for (int c = 0; c < CDIM; c++) {
            float zv = xrow[(size_t)c * HW + tid];
            s = __fadd_rn(s, __fmul_rn(zv, zv));
        }
        Zs[tid] = s;
    }
    __syncthreads();

    // ---- A fragments: 2 halves x 4 k-steps ----
    const int m_base = w * 16;
    const int g      = lane >> 2;
    const int t4     = lane & 3;
    u32 afr[2][4][4];
    {
        int a_r = lane & 15, a_c8 = (lane >> 4) << 3;
        u32 xm  = (u32)((a_r & 7) << 4);
        #pragma unroll
        for (int h = 0; h < 2; h++) {
            u32 lin = sb + OFF_A(h) + (u32)((m_base + a_r) * 128 + a_c8 * 2);
            #pragma unroll
            for (int ks = 0; ks < 4; ks++)
                ldsm4((lin + ks * 32) ^ xm,
                      afr[h][ks][0], afr[h][ks][1], afr[h][ks][2], afr[h][ks][3]);
        }
    }

    const int b_r = (lane & 7) + ((lane >> 4) << 3);
    const int b_c = ((lane >> 3) & 1) << 3;
    const u32 bxm  = (u32)((b_r & 7) << 4);
    const u32 blin = sb + OFF_B1 + (u32)(b_r * 128 + b_c * 2);

    float mA1 = 1e30f, mA2 = 1e30f;      // row m_base+g   (embedded s values)
    float mB1 = 1e30f, mB2 = 1e30f;      // row m_base+g+8
    const float UNSC = 0.00006103515625f;    // 2^-14 (a*16, e*1024)

    #pragma unroll 1
    for (int nc = 0; nc < 16; nc++) {    // 32 codewords per chunk, all 512 in smem
        float acc[4][4];
        #pragma unroll
        for (int i = 0; i < 4; i++)
            #pragma unroll
            for (int j = 0; j < 4; j++) acc[i][j] = 0.0f;

        #pragma unroll
        for (int ks = 0; ks < 4; ks++) {
            #pragma unroll
            for (int pr = 0; pr < 2; pr++) {
                u32 off = (u32)(nc * 4096 + pr * 2048 + ks * 32);
                u32 c0, c1, c2, c3;
                ldsm4((blin + off) ^ bxm, c0, c1, c2, c3);
                mma_f16(acc[2 * pr],     afr[0][ks], c0, c1);   // a1.e1
                mma_f16(acc[2 * pr],     afr[1][ks], c0, c1);   // a2.e1
                mma_f16(acc[2 * pr + 1], afr[0][ks], c2, c3);
                mma_f16(acc[2 * pr + 1], afr[1][ks], c2, c3);
            }
        }
        #pragma unroll
        for (int nt = 0; nt < 4; nt++) {
            int col0 = nc * 32 + nt * 8 + 2 * t4;
            float e20 = e2s[col0], e21 = e2s[col0 + 1];
            upd2(mA1, mA2, embed(__fmaf_rn(acc[nt][0], UNSC, e20), col0));
            upd2(mA1, mA2, embed(__fmaf_rn(acc[nt][1], UNSC, e21), col0 + 1));
            upd2(mB1, mB2, embed(__fmaf_rn(acc[nt][2], UNSC, e20), col0));
            upd2(mB1, mB2, embed(__fmaf_rn(acc[nt][3], UNSC, e21), col0 + 1));
        }
    }

    // quad reduce (lanes share a row across t4)
    #pragma unroll
    for (int o = 1; o <= 2; o <<= 1) {
        float a1 = __shfl_xor_sync(0xffffffffu, mA1, o);
        float a2 = __shfl_xor_sync(0xffffffffu, mA2, o);
        float hA = fmaxf(mA1, a1);
        mA1 = fminf(mA1, a1);
        mA2 = fminf(fminf(mA2, a2), hA);
        float b1 = __shfl_xor_sync(0xffffffffu, mB1, o);
        float b2 = __shfl_xor_sync(0xffffffffu, mB2, o);
        float hB = fmaxf(mB1, b1);
        mB1 = fminf(mB1, b1);
        mB2 = fminf(fminf(mB2, b2), hB);
    }
    if (t4 == 0) {
        float em = __fsqrt_rn(__uint_as_float(g_em2));
        int r0 = m_base + g, r1 = m_base + g + 8;
        float mg0 = __fmaf_rn(4.0f * __fsqrt_rn(Zs[r0]), em, 5e-5f);
        float mg1 = __fmaf_rn(4.0f * __fsqrt_rn(Zs[r1]), em, 5e-5f);
        kbs[r0] = __float_as_uint(mA1) & 511u;
        kbs[r1] = __float_as_uint(mB1) & 511u;
        fls[r0] = (mA2 - mA1) < mg0;
        fls[r1] = (mB2 - mB1) < mg1;
    }
    __syncwarp();

    // ---- exact rescore of flagged rows: coalesced via g_cbT[c][k] ----
    for (int r = 0; r < 16; r++) {
        int row = m_base + r;
        if (!fls[row]) continue;
        const float* xz = xrow + row;
        float Zp = Zs[row];
        u64 best = ~0ull;
        #pragma unroll 1
        for (int jj = 0; jj < 4; jj++) {
            int k0 = lane + 128 * jj;                 // + 0,32,64,96 below
            float m0 = 0.f, m1 = 0.f, m2 = 0.f, m3 = 0.f;
            #pragma unroll
            for (int c = 0; c < CDIM; c++) {          // c ascending per chain
                float zc = __ldg(xz + (size_t)c * HW);
                const float* ct = g_cbT + c * KCODES + k0;
                m0 = __fmaf_rn(zc, __ldg(ct),      m0);   // lanes consecutive k
                m1 = __fmaf_rn(zc, __ldg(ct + 32), m1);
                m2 = __fmaf_rn(zc, __ldg(ct + 64), m2);
                m3 = __fmaf_rn(zc, __ldg(ct + 96), m3);
            }
            float mm[4] = { m0, m1, m2, m3 };
            #pragma unroll
            for (int i = 0; i < 4; i++) {
                int k = k0 + 32 * i;
                float tt = __fadd_rn(Zp, e2s[k]);
                float d  = __fadd_rn(tt, -2.0f * mm[i]);
                u64 key = ((u64)__float_as_uint(d) << 32) | (u32)k;   // d > 0
                if (key < best) best = key;
            }
        }
        #pragma unroll
        for (int o = 16; o; o >>= 1) {
            u64 v = __shfl_xor_sync(0xffffffffu, best, o);
            if (v < best) best = v;
        }
        if (lane == 0) kbs[row] = (u32)(best & 0x1FFu);
    }
    __syncthreads();   // kbs final; B tile dead -> qsm may overwrite

    // ---- stage winning codewords into smem, coalesced ----
    for (int i = 0; i < 16; i++) {
        int row = m_base + i;
        const float* src = cb + (size_t)kbs[row] * CDIM;
        qsm[row * QPITCH + lane]      = __ldg(src + lane);
        qsm[row * QPITCH + lane + 32] = __ldg(src + lane + 32);
    }
    __syncthreads();

    // ---- writeback: straight-through RN(x + RN(q-x)) + SSE, q from smem ----
    {
        int p = tid & 127, ch = tid >> 7;
        float* op = out + (size_t)b * CDIM * HW + hw0 + p;
        const float* ip = xrow + p;
        const float* qp = qsm + p * QPITCH;
        float sse = 0.0f;
        #pragma unroll 8
        for (int c = ch * 32; c < ch * 32 + 32; c++) {
            float zv   = __ldg(ip + (size_t)c * HW);
            float qv   = qp[c];                        // LDS, conflict-free
            float diff = __fadd_rn(qv, -zv);
            op[(size_t)c * HW] = __fadd_rn(zv, diff);
            sse = __fadd_rn(sse, __fmul_rn(diff, diff));
        }
        #pragma unroll
        for (int o = 16; o; o >>= 1) sse += __shfl_xor_sync(0xffffffffu, sse, o);
        if (lane == 0) atomicAdd(&g_loss_sum, sse);
    }

    // ---- fused finalize, reset for next graph replay ----
    __syncthreads();
    if (tid == 0) {
        __threadfence();
        u32 done = atomicAdd(&g_done, 1u);
        if (done == gridDim.x - 1) {
            float L = atomicAdd(&g_loss_sum, 0.0f) * (1.0f / (float)NELEM);
            if (loss_idx >= 0)
                out[loss_idx] = __fadd_rn(L, 0.25f * L);
            g_loss_sum = 0.0f;
            g_done     = 0u;
            __threadfence();
        }
    }
}

extern "C" void kernel_launch(void* const* d_in, const int* in_sizes, int n_in,
                              void* d_out, int out_size) {
    const float* x   = (const float*)d_in[0];
    const float* cb  = (const float*)d_in[1];
    float*       out = (float*)d_out;

    cudaFuncSetAttribute(vq_main_kernel,
                         cudaFuncAttributeMaxDynamicSharedMemorySize, SMEM_SZ);
    int loss_idx = (out_size > NELEM) ? (out_size - 1) : -1;
    vq_prep_kernel<<<128, THREADS>>>(cb);
    vq_main_kernel<<<GRIDSZ, THREADS, SMEM_SZ>>>(x, cb, out, loss_idx);
}